// round 1
// baseline (speedup 1.0000x reference)
#include <cuda_runtime.h>
#include <cuda_bf16.h>
#include <math.h>

// Problem constants
#define BATCH   2
#define SEQ     2048
#define HIDDEN  1024
#define NHEADS  16
#define HD      64            // head dim
#define NROWS   (BATCH*SEQ)   // 4096
#define EPS     1e-5f

// Scratch (device globals: no allocation allowed)
__device__ float g_qkv[3ull * NROWS * HIDDEN];   // [which][bh][s][e] head-split layout
__device__ float g_ao [1ull * NROWS * HIDDEN];   // attention out, [b][s][d] layout

// ---------------------------------------------------------------------------
// Kernel 1: fused QKV projection.  C = x @ W^T, written head-split.
// Tiles: BM=64, BN=64 (== one head), BK=16. 256 threads, 4x4 micro-tile.
// ---------------------------------------------------------------------------
__global__ __launch_bounds__(256) void qkv_gemm_kernel(
    const float* __restrict__ x,
    const float* __restrict__ Wq,
    const float* __restrict__ Wk,
    const float* __restrict__ Wv)
{
    const int which = blockIdx.z;
    const float* __restrict__ W = (which == 0) ? Wq : (which == 1) ? Wk : Wv;
    float* __restrict__ C = g_qkv + (size_t)which * NROWS * HIDDEN;

    const int bm = blockIdx.x;   // 0..63  (row tile of 64)
    const int bn = blockIdx.y;   // 0..15  (head)

    __shared__ float As[16][64];  // As[k][m]  (transposed stage)
    __shared__ float Bs[16][64];  // Bs[k][n]

    const int tid = threadIdx.x;
    const int tx = tid & 15;
    const int ty = tid >> 4;

    float acc[4][4];
    #pragma unroll
    for (int i = 0; i < 4; i++)
        #pragma unroll
        for (int j = 0; j < 4; j++) acc[i][j] = 0.f;

    const int lr  = tid >> 2;          // 0..63 : row within tile to load
    const int lk  = (tid & 3) << 2;    // 0,4,8,12 : k offset (float4)

    for (int k0 = 0; k0 < HIDDEN; k0 += 16) {
        __syncthreads();
        {
            float4 av = *(const float4*)&x[(size_t)(bm*64 + lr)*HIDDEN + k0 + lk];
            As[lk  ][lr] = av.x; As[lk+1][lr] = av.y;
            As[lk+2][lr] = av.z; As[lk+3][lr] = av.w;
            float4 bv = *(const float4*)&W[(size_t)(bn*64 + lr)*HIDDEN + k0 + lk];
            Bs[lk  ][lr] = bv.x; Bs[lk+1][lr] = bv.y;
            Bs[lk+2][lr] = bv.z; Bs[lk+3][lr] = bv.w;
        }
        __syncthreads();
        #pragma unroll
        for (int k = 0; k < 16; k++) {
            float4 a4 = *(const float4*)&As[k][4*ty];
            float4 b4 = *(const float4*)&Bs[k][4*tx];
            float a[4] = {a4.x, a4.y, a4.z, a4.w};
            float b[4] = {b4.x, b4.y, b4.z, b4.w};
            #pragma unroll
            for (int i = 0; i < 4; i++)
                #pragma unroll
                for (int j = 0; j < 4; j++)
                    acc[i][j] = fmaf(a[i], b[j], acc[i][j]);
        }
    }

    // Write head-split: C[((b*16 + h)*SEQ + s)*HD + e],  h == bn
    #pragma unroll
    for (int i = 0; i < 4; i++) {
        int row = bm*64 + 4*ty + i;          // 0..4095
        int b   = row >> 11;                 // /2048
        int s   = row & 2047;
        size_t base = (((size_t)(b*NHEADS + bn))*SEQ + s)*HD + 4*tx;
        float4 v = make_float4(acc[i][0], acc[i][1], acc[i][2], acc[i][3]);
        *(float4*)&C[base] = v;
    }
}

// ---------------------------------------------------------------------------
// Kernel 2: flash attention.  One block = 64 queries of one (b,h).
// Streams 32-key tiles, online softmax. 256 threads.
//   S micro-tile: rows 4*ty+i (i<4), cols 2*tx+j (j<2)
//   O micro-tile: rows 4*ty+i,        dims 4*tx+j (j<4)
// ---------------------------------------------------------------------------
#define BQ   64
#define BKEY 32

__global__ __launch_bounds__(256) void attn_kernel()
{
    __shared__ float Qs[BQ  ][HD+1];    // 64x65
    __shared__ float Ks[BKEY][HD+1];    // 32x65
    __shared__ float Vs[BKEY][HD+1];    // 32x65
    __shared__ float Ps[BQ  ][BKEY+1];  // 64x33

    const int tid = threadIdx.x;
    const int tx  = tid & 15;
    const int ty  = tid >> 4;
    const int bh  = blockIdx.y;          // 0..31
    const int q0  = blockIdx.x * BQ;     // query tile start

    const float* __restrict__ Qb = g_qkv + 0ull*NROWS*HIDDEN + (size_t)bh*SEQ*HD;
    const float* __restrict__ Kb = g_qkv + 1ull*NROWS*HIDDEN + (size_t)bh*SEQ*HD;
    const float* __restrict__ Vb = g_qkv + 2ull*NROWS*HIDDEN + (size_t)bh*SEQ*HD;

    // Load Q tile (64x64): 16 float4 per row
    for (int i = tid; i < BQ*HD/4; i += 256) {
        int r  = i >> 4;
        int c4 = (i & 15) << 2;
        float4 v = *(const float4*)&Qb[(size_t)(q0 + r)*HD + c4];
        Qs[r][c4] = v.x; Qs[r][c4+1] = v.y; Qs[r][c4+2] = v.z; Qs[r][c4+3] = v.w;
    }

    float o[4][4];
    #pragma unroll
    for (int i = 0; i < 4; i++)
        #pragma unroll
        for (int j = 0; j < 4; j++) o[i][j] = 0.f;
    float m_r[4] = {-1e30f, -1e30f, -1e30f, -1e30f};
    float l_r[4] = {0.f, 0.f, 0.f, 0.f};

    const float scale = 0.125f;  // 1/sqrt(64)

    for (int kt = 0; kt < SEQ; kt += BKEY) {
        __syncthreads();   // prev iter done with Ks/Vs/Ps; Qs visible (1st iter)
        // Load K,V tiles (32x64 each): 512 float4 each, 2 per thread
        for (int i = tid; i < BKEY*HD/4; i += 256) {
            int r  = i >> 4;
            int c4 = (i & 15) << 2;
            float4 kv = *(const float4*)&Kb[(size_t)(kt + r)*HD + c4];
            Ks[r][c4] = kv.x; Ks[r][c4+1] = kv.y; Ks[r][c4+2] = kv.z; Ks[r][c4+3] = kv.w;
            float4 vv = *(const float4*)&Vb[(size_t)(kt + r)*HD + c4];
            Vs[r][c4] = vv.x; Vs[r][c4+1] = vv.y; Vs[r][c4+2] = vv.z; Vs[r][c4+3] = vv.w;
        }
        __syncthreads();

        // S = scale * Q K^T   (4 rows x 2 cols per thread)
        float s[4][2];
        #pragma unroll
        for (int i = 0; i < 4; i++) { s[i][0] = 0.f; s[i][1] = 0.f; }
        #pragma unroll 16
        for (int d = 0; d < HD; d++) {
            float k0 = Ks[2*tx    ][d];
            float k1 = Ks[2*tx + 1][d];
            #pragma unroll
            for (int i = 0; i < 4; i++) {
                float q = Qs[4*ty + i][d];
                s[i][0] = fmaf(q, k0, s[i][0]);
                s[i][1] = fmaf(q, k1, s[i][1]);
            }
        }

        // Online softmax update per owned row
        float alpha[4];
        #pragma unroll
        for (int i = 0; i < 4; i++) {
            s[i][0] *= scale;
            s[i][1] *= scale;
            float mt = fmaxf(s[i][0], s[i][1]);
            #pragma unroll
            for (int off = 8; off > 0; off >>= 1)
                mt = fmaxf(mt, __shfl_xor_sync(0xffffffffu, mt, off, 16));
            float mnew = fmaxf(m_r[i], mt);
            float p0 = __expf(s[i][0] - mnew);
            float p1 = __expf(s[i][1] - mnew);
            Ps[4*ty + i][2*tx    ] = p0;
            Ps[4*ty + i][2*tx + 1] = p1;
            float ls = p0 + p1;
            #pragma unroll
            for (int off = 8; off > 0; off >>= 1)
                ls += __shfl_xor_sync(0xffffffffu, ls, off, 16);
            alpha[i] = __expf(m_r[i] - mnew);
            l_r[i] = l_r[i] * alpha[i] + ls;
            m_r[i] = mnew;
        }
        #pragma unroll
        for (int i = 0; i < 4; i++)
            #pragma unroll
            for (int j = 0; j < 4; j++) o[i][j] *= alpha[i];

        __syncthreads();   // Ps visible to all

        // O += P @ V   (inner over 32 keys)
        #pragma unroll 8
        for (int c = 0; c < BKEY; c++) {
            float v0 = Vs[c][4*tx    ];
            float v1 = Vs[c][4*tx + 1];
            float v2 = Vs[c][4*tx + 2];
            float v3 = Vs[c][4*tx + 3];
            #pragma unroll
            for (int i = 0; i < 4; i++) {
                float p = Ps[4*ty + i][c];
                o[i][0] = fmaf(p, v0, o[i][0]);
                o[i][1] = fmaf(p, v1, o[i][1]);
                o[i][2] = fmaf(p, v2, o[i][2]);
                o[i][3] = fmaf(p, v3, o[i][3]);
            }
        }
    }

    // Epilogue: normalize and write in [b][s][hidden] layout
    const int b = bh >> 4;
    const int h = bh & 15;
    #pragma unroll
    for (int i = 0; i < 4; i++) {
        float inv_l = 1.f / l_r[i];
        int s_idx = q0 + 4*ty + i;
        size_t base = ((size_t)(b*SEQ + s_idx))*HIDDEN + h*HD + 4*tx;
        float4 v = make_float4(o[i][0]*inv_l, o[i][1]*inv_l,
                               o[i][2]*inv_l, o[i][3]*inv_l);
        *(float4*)&g_ao[base] = v;
    }
}

// ---------------------------------------------------------------------------
// Kernel 3: residual + LayerNorm. One block per row (4096 rows).
// ---------------------------------------------------------------------------
__global__ __launch_bounds__(256) void ln_kernel(
    const float* __restrict__ x,
    const float* __restrict__ gamma,
    const float* __restrict__ beta,
    float* __restrict__ out)
{
    const int row = blockIdx.x;
    const float* __restrict__ a  = g_ao + (size_t)row * HIDDEN;
    const float* __restrict__ xr = x    + (size_t)row * HIDDEN;
    float*       __restrict__ orow = out + (size_t)row * HIDDEN;

    const int tid = threadIdx.x;
    float4 av = *(const float4*)&a [tid*4];
    float4 xv = *(const float4*)&xr[tid*4];
    float h0 = av.x + xv.x, h1 = av.y + xv.y, h2 = av.z + xv.z, h3 = av.w + xv.w;

    float sum  = h0 + h1 + h2 + h3;
    float sum2 = h0*h0 + h1*h1 + h2*h2 + h3*h3;

    // Block reduce (8 warps)
    __shared__ float red[2][8];
    #pragma unroll
    for (int off = 16; off > 0; off >>= 1) {
        sum  += __shfl_xor_sync(0xffffffffu, sum,  off);
        sum2 += __shfl_xor_sync(0xffffffffu, sum2, off);
    }
    int warp = tid >> 5, lane = tid & 31;
    if (lane == 0) { red[0][warp] = sum; red[1][warp] = sum2; }
    __syncthreads();
    if (warp == 0) {
        float s  = (lane < 8) ? red[0][lane] : 0.f;
        float s2 = (lane < 8) ? red[1][lane] : 0.f;
        #pragma unroll
        for (int off = 4; off > 0; off >>= 1) {
            s  += __shfl_xor_sync(0xffffffffu, s,  off);
            s2 += __shfl_xor_sync(0xffffffffu, s2, off);
        }
        if (lane == 0) { red[0][0] = s; red[1][0] = s2; }
    }
    __syncthreads();
    float mean = red[0][0] * (1.f / HIDDEN);
    float var  = red[1][0] * (1.f / HIDDEN) - mean*mean;
    float rstd = rsqrtf(var + EPS);

    float4 gv = *(const float4*)&gamma[tid*4];
    float4 bv = *(const float4*)&beta [tid*4];
    float4 ov;
    ov.x = (h0 - mean) * rstd * gv.x + bv.x;
    ov.y = (h1 - mean) * rstd * gv.y + bv.y;
    ov.z = (h2 - mean) * rstd * gv.z + bv.z;
    ov.w = (h3 - mean) * rstd * gv.w + bv.w;
    *(float4*)&orow[tid*4] = ov;
}

// ---------------------------------------------------------------------------
extern "C" void kernel_launch(void* const* d_in, const int* in_sizes, int n_in,
                              void* d_out, int out_size)
{
    const float* x     = (const float*)d_in[0];
    const float* Wq    = (const float*)d_in[1];
    const float* Wk    = (const float*)d_in[2];
    const float* Wv    = (const float*)d_in[3];
    const float* gamma = (const float*)d_in[4];
    const float* beta  = (const float*)d_in[5];
    float* out = (float*)d_out;

    qkv_gemm_kernel<<<dim3(NROWS/64, HIDDEN/64, 3), 256>>>(x, Wq, Wk, Wv);
    attn_kernel<<<dim3(SEQ/BQ, BATCH*NHEADS), 256>>>();
    ln_kernel<<<NROWS, 256>>>(x, gamma, beta, out);
}

// round 2
// speedup vs baseline: 6.8630x; 6.8630x over previous
#include <cuda_runtime.h>
#include <cuda_fp16.h>
#include <math.h>

#define BATCH   2
#define SEQ     2048
#define HIDDEN  1024
#define NHEADS  16
#define HD      64
#define NROWS   (BATCH*SEQ)   // 4096
#define EPS     1e-5f

// Scratch (device globals: no allocation allowed)
__device__ __align__(16) __half g_xh[(size_t)NROWS * HIDDEN];
__device__ __align__(16) __half g_wh[3ull * HIDDEN * HIDDEN];
__device__ __align__(16) __half g_q [(size_t)NROWS * HIDDEN];  // [bh][s][64]
__device__ __align__(16) __half g_k [(size_t)NROWS * HIDDEN];
__device__ __align__(16) __half g_v [(size_t)NROWS * HIDDEN];
__device__ __align__(16) float  g_ao[(size_t)NROWS * HIDDEN];  // [b][s][1024]

// ---------------------------------------------------------------------------
// MMA / ldmatrix helpers
// ---------------------------------------------------------------------------
__device__ __forceinline__ void mma16816(float* c, const unsigned* a, const unsigned* b) {
    asm volatile(
        "mma.sync.aligned.m16n8k16.row.col.f32.f16.f16.f32 "
        "{%0,%1,%2,%3}, {%4,%5,%6,%7}, {%8,%9}, {%0,%1,%2,%3};\n"
        : "+f"(c[0]), "+f"(c[1]), "+f"(c[2]), "+f"(c[3])
        : "r"(a[0]), "r"(a[1]), "r"(a[2]), "r"(a[3]), "r"(b[0]), "r"(b[1]));
}

__device__ __forceinline__ void ldsm4(unsigned* r, const void* p) {
    unsigned addr = (unsigned)__cvta_generic_to_shared(p);
    asm volatile("ldmatrix.sync.aligned.m8n8.x4.shared.b16 {%0,%1,%2,%3}, [%4];"
                 : "=r"(r[0]), "=r"(r[1]), "=r"(r[2]), "=r"(r[3]) : "r"(addr));
}

__device__ __forceinline__ void ldsm4t(unsigned* r, const void* p) {
    unsigned addr = (unsigned)__cvta_generic_to_shared(p);
    asm volatile("ldmatrix.sync.aligned.m8n8.x4.trans.shared.b16 {%0,%1,%2,%3}, [%4];"
                 : "=r"(r[0]), "=r"(r[1]), "=r"(r[2]), "=r"(r[3]) : "r"(addr));
}

// ---------------------------------------------------------------------------
// Kernel 0: fp32 -> fp16 conversion of x and the three weight matrices
// ---------------------------------------------------------------------------
__global__ __launch_bounds__(256) void convert_kernel(
    const float* __restrict__ x,  const float* __restrict__ wq,
    const float* __restrict__ wk, const float* __restrict__ wv)
{
    const float* src; __half* dst; int n4;
    switch (blockIdx.y) {
        case 0:  src = x;  dst = g_xh;                       n4 = NROWS*HIDDEN/4;  break;
        case 1:  src = wq; dst = g_wh;                       n4 = HIDDEN*HIDDEN/4; break;
        case 2:  src = wk; dst = g_wh + 1ull*HIDDEN*HIDDEN;  n4 = HIDDEN*HIDDEN/4; break;
        default: src = wv; dst = g_wh + 2ull*HIDDEN*HIDDEN;  n4 = HIDDEN*HIDDEN/4; break;
    }
    int stride = gridDim.x * 256;
    for (int j = blockIdx.x*256 + threadIdx.x; j < n4; j += stride) {
        float4 v = ((const float4*)src)[j];
        __half2 h0 = __floats2half2_rn(v.x, v.y);
        __half2 h1 = __floats2half2_rn(v.z, v.w);
        ((__half2*)dst)[2*j]   = h0;
        ((__half2*)dst)[2*j+1] = h1;
    }
}

// ---------------------------------------------------------------------------
// Kernel 1: QKV GEMM on tensor cores.  C = Xh @ Wh^T, written head-split fp16.
// BM=128, BN=128, BK=32, 256 threads (8 warps, 2x4), warp tile 64x32.
// ---------------------------------------------------------------------------
__global__ __launch_bounds__(256) void qkv_gemm_kernel()
{
    const int which = blockIdx.z;
    const __half* __restrict__ W = g_wh + (size_t)which * HIDDEN * HIDDEN;

    __shared__ __align__(16) __half As[128][40];   // stride 80B: conflict-free ldmatrix
    __shared__ __align__(16) __half Bs[128][40];

    const int tid  = threadIdx.x;
    const int lane = tid & 31, warp = tid >> 5;
    const int wm = warp >> 2, wn = warp & 3;       // 2 x 4 warp grid
    const int bm = blockIdx.x, bn = blockIdx.y;

    float acc[4][4][4] = {};

    const int lr0 = tid >> 2;            // load row (0..63), +64 for second chunk
    const int lo0 = (tid & 3) * 8;       // half-offset within 32-wide k slab
    const __half* Abase = g_xh + (size_t)(bm*128) * HIDDEN;
    const __half* Bbase = W    + (size_t)(bn*128) * HIDDEN;

    uint4 ra0 = *(const uint4*)(Abase + (size_t)lr0      * HIDDEN + lo0);
    uint4 ra1 = *(const uint4*)(Abase + (size_t)(lr0+64) * HIDDEN + lo0);
    uint4 rb0 = *(const uint4*)(Bbase + (size_t)lr0      * HIDDEN + lo0);
    uint4 rb1 = *(const uint4*)(Bbase + (size_t)(lr0+64) * HIDDEN + lo0);

    for (int k0 = 0; k0 < HIDDEN; k0 += 32) {
        __syncthreads();
        *(uint4*)&As[lr0   ][lo0] = ra0;
        *(uint4*)&As[lr0+64][lo0] = ra1;
        *(uint4*)&Bs[lr0   ][lo0] = rb0;
        *(uint4*)&Bs[lr0+64][lo0] = rb1;
        __syncthreads();

        if (k0 + 32 < HIDDEN) {
            int kn = k0 + 32 + lo0;
            ra0 = *(const uint4*)(Abase + (size_t)lr0      * HIDDEN + kn);
            ra1 = *(const uint4*)(Abase + (size_t)(lr0+64) * HIDDEN + kn);
            rb0 = *(const uint4*)(Bbase + (size_t)lr0      * HIDDEN + kn);
            rb1 = *(const uint4*)(Bbase + (size_t)(lr0+64) * HIDDEN + kn);
        }

        #pragma unroll
        for (int ks = 0; ks < 2; ks++) {
            unsigned aF[4][4], bF[4][2];
            #pragma unroll
            for (int mt = 0; mt < 4; mt++)
                ldsm4(aF[mt], &As[wm*64 + mt*16 + (lane & 15)][ks*16 + (lane >> 4)*8]);
            #pragma unroll
            for (int np = 0; np < 2; np++) {
                unsigned r[4];
                ldsm4(r, &Bs[wn*32 + np*16 + ((lane >> 4) << 3) + (lane & 7)]
                           [ks*16 + ((lane >> 3) & 1)*8]);
                bF[np*2  ][0] = r[0]; bF[np*2  ][1] = r[1];
                bF[np*2+1][0] = r[2]; bF[np*2+1][1] = r[3];
            }
            #pragma unroll
            for (int mt = 0; mt < 4; mt++)
                #pragma unroll
                for (int nt = 0; nt < 4; nt++)
                    mma16816(acc[mt][nt], aF[mt], bF[nt]);
        }
    }

    // Epilogue: write fp16 head-split [bh][s][e]
    __half* dst = (which == 0) ? g_q : (which == 1) ? g_k : g_v;
    #pragma unroll
    for (int mt = 0; mt < 4; mt++) {
        int row_base = bm*128 + wm*64 + mt*16 + (lane >> 2);
        #pragma unroll
        for (int i = 0; i < 2; i++) {
            int row = row_base + i*8;
            int b = row >> 11, s = row & 2047;
            #pragma unroll
            for (int nt = 0; nt < 4; nt++) {
                int col = bn*128 + wn*32 + nt*8 + (lane & 3)*2;
                int h = col >> 6, e = col & 63;
                __half2 hv = __floats2half2_rn(acc[mt][nt][i*2], acc[mt][nt][i*2+1]);
                *(__half2*)&dst[(((size_t)(b*NHEADS + h))*SEQ + s)*HD + e] = hv;
            }
        }
    }
}

// ---------------------------------------------------------------------------
// Kernel 2: flash attention on tensor cores.
// Block = 128 queries of one (b,h). 8 warps, warp = 16 q rows.
// Key tiles of 64. S and O accumulated in fp32 MMA frags; P repacked in regs.
// ---------------------------------------------------------------------------
__global__ __launch_bounds__(256) void attn_kernel()
{
    __shared__ __align__(16) __half Ks[64][72];  // stride 144B: conflict-free
    __shared__ __align__(16) __half Vs[64][72];

    const int tid = threadIdx.x, lane = tid & 31, w = tid >> 5;
    const int bh = blockIdx.y;
    const int q0 = blockIdx.x * 128;

    const __half* __restrict__ Qb = g_q + (size_t)bh * SEQ * HD;
    const __half* __restrict__ Kb = g_k + (size_t)bh * SEQ * HD;
    const __half* __restrict__ Vb = g_v + (size_t)bh * SEQ * HD;

    // Stage Q tile (128x64) through Ks/Vs, pull into A-frags, then release smem
    #pragma unroll
    for (int i = 0; i < 4; i++) {
        int cid = tid + 256*i;                  // 1024 chunks of 8 halves
        int r = cid >> 3, off = (cid & 7) * 8;
        uint4 v = *(const uint4*)(Qb + (size_t)(q0 + r)*HD + off);
        if (r < 64) *(uint4*)&Ks[r][off] = v;
        else        *(uint4*)&Vs[r-64][off] = v;
    }
    __syncthreads();
    unsigned qF[4][4];
    {
        int qr = w*16 + (lane & 15);
        const __half* qrow = (qr < 64) ? &Ks[qr][0] : &Vs[qr-64][0];
        #pragma unroll
        for (int kk = 0; kk < 4; kk++)
            ldsm4(qF[kk], qrow + kk*16 + (lane >> 4)*8);
    }

    float o[8][4] = {};
    float mrow[2] = {-1e30f, -1e30f};
    float lrow[2] = {0.f, 0.f};

    for (int it = 0; it < SEQ/64; it++) {
        __syncthreads();
        #pragma unroll
        for (int i = 0; i < 2; i++) {
            int cid = tid + 256*i;              // 512 chunks of 8 halves
            int r = cid >> 3, off = (cid & 7) * 8;
            *(uint4*)&Ks[r][off] = *(const uint4*)(Kb + (size_t)(it*64 + r)*HD + off);
            *(uint4*)&Vs[r][off] = *(const uint4*)(Vb + (size_t)(it*64 + r)*HD + off);
        }
        __syncthreads();

        // S = Q K^T  (warp: 16 q x 64 keys; 8 n-tiles of 8 keys)
        float sc[8][4] = {};
        #pragma unroll
        for (int kk = 0; kk < 4; kk++) {
            #pragma unroll
            for (int np = 0; np < 4; np++) {
                unsigned r[4];
                ldsm4(r, &Ks[np*16 + ((lane >> 4) << 3) + (lane & 7)]
                           [kk*16 + ((lane >> 3) & 1)*8]);
                unsigned b0[2] = {r[0], r[1]}, b1[2] = {r[2], r[3]};
                mma16816(sc[np*2  ], qF[kk], b0);
                mma16816(sc[np*2+1], qF[kk], b1);
            }
        }

        // Online softmax (thread owns rows lane>>2 and +8; quad lanes hold cols)
        float mt0 = -1e30f, mt1 = -1e30f;
        #pragma unroll
        for (int nt = 0; nt < 8; nt++) {
            #pragma unroll
            for (int j = 0; j < 4; j++) sc[nt][j] *= 0.125f;
            mt0 = fmaxf(mt0, fmaxf(sc[nt][0], sc[nt][1]));
            mt1 = fmaxf(mt1, fmaxf(sc[nt][2], sc[nt][3]));
        }
        mt0 = fmaxf(mt0, __shfl_xor_sync(0xffffffffu, mt0, 1));
        mt0 = fmaxf(mt0, __shfl_xor_sync(0xffffffffu, mt0, 2));
        mt1 = fmaxf(mt1, __shfl_xor_sync(0xffffffffu, mt1, 1));
        mt1 = fmaxf(mt1, __shfl_xor_sync(0xffffffffu, mt1, 2));
        float mn0 = fmaxf(mrow[0], mt0), mn1 = fmaxf(mrow[1], mt1);
        float a0 = __expf(mrow[0] - mn0), a1 = __expf(mrow[1] - mn1);

        float s0 = 0.f, s1 = 0.f;
        unsigned ph0[8], ph1[8];
        #pragma unroll
        for (int nt = 0; nt < 8; nt++) {
            float p0 = __expf(sc[nt][0] - mn0), p1 = __expf(sc[nt][1] - mn0);
            float p2 = __expf(sc[nt][2] - mn1), p3 = __expf(sc[nt][3] - mn1);
            s0 += p0 + p1;  s1 += p2 + p3;
            __half2 h0 = __floats2half2_rn(p0, p1); ph0[nt] = *(unsigned*)&h0;
            __half2 h1 = __floats2half2_rn(p2, p3); ph1[nt] = *(unsigned*)&h1;
        }
        s0 += __shfl_xor_sync(0xffffffffu, s0, 1);
        s0 += __shfl_xor_sync(0xffffffffu, s0, 2);
        s1 += __shfl_xor_sync(0xffffffffu, s1, 1);
        s1 += __shfl_xor_sync(0xffffffffu, s1, 2);
        lrow[0] = lrow[0]*a0 + s0;  lrow[1] = lrow[1]*a1 + s1;
        mrow[0] = mn0;  mrow[1] = mn1;
        #pragma unroll
        for (int nt = 0; nt < 8; nt++) {
            o[nt][0] *= a0; o[nt][1] *= a0; o[nt][2] *= a1; o[nt][3] *= a1;
        }

        // O += P @ V  (P A-frags assembled from S accum regs — no smem trip)
        #pragma unroll
        for (int kt = 0; kt < 4; kt++) {
            unsigned aP[4] = {ph0[2*kt], ph1[2*kt], ph0[2*kt+1], ph1[2*kt+1]};
            #pragma unroll
            for (int np = 0; np < 4; np++) {
                unsigned r[4];
                ldsm4t(r, &Vs[kt*16 + (lane & 7) + ((lane >> 3) & 1)*8]
                            [np*16 + (lane >> 4)*8]);
                unsigned b0[2] = {r[0], r[1]}, b1[2] = {r[2], r[3]};
                mma16816(o[np*2  ], aP, b0);
                mma16816(o[np*2+1], aP, b1);
            }
        }
    }

    // Epilogue: normalize, write fp32 [b][s][hidden]
    const int b = bh >> 4, h = bh & 15;
    float inv0 = 1.f / lrow[0], inv1 = 1.f / lrow[1];
    int r0g = q0 + w*16 + (lane >> 2);
    #pragma unroll
    for (int nt = 0; nt < 8; nt++) {
        int e = h*HD + nt*8 + (lane & 3)*2;
        float2 v0 = make_float2(o[nt][0]*inv0, o[nt][1]*inv0);
        float2 v1 = make_float2(o[nt][2]*inv1, o[nt][3]*inv1);
        *(float2*)&g_ao[((size_t)(b*SEQ + r0g    ))*HIDDEN + e] = v0;
        *(float2*)&g_ao[((size_t)(b*SEQ + r0g + 8))*HIDDEN + e] = v1;
    }
}

// ---------------------------------------------------------------------------
// Kernel 3: residual + LayerNorm. One block per row.
// ---------------------------------------------------------------------------
__global__ __launch_bounds__(256) void ln_kernel(
    const float* __restrict__ x,
    const float* __restrict__ gamma,
    const float* __restrict__ beta,
    float* __restrict__ out)
{
    const int row = blockIdx.x;
    const float* __restrict__ a  = g_ao + (size_t)row * HIDDEN;
    const float* __restrict__ xr = x    + (size_t)row * HIDDEN;
    float*       __restrict__ orow = out + (size_t)row * HIDDEN;

    const int tid = threadIdx.x;
    float4 av = *(const float4*)&a [tid*4];
    float4 xv = *(const float4*)&xr[tid*4];
    float h0 = av.x + xv.x, h1 = av.y + xv.y, h2 = av.z + xv.z, h3 = av.w + xv.w;

    float sum  = h0 + h1 + h2 + h3;
    float sum2 = h0*h0 + h1*h1 + h2*h2 + h3*h3;

    __shared__ float red[2][8];
    #pragma unroll
    for (int off = 16; off > 0; off >>= 1) {
        sum  += __shfl_xor_sync(0xffffffffu, sum,  off);
        sum2 += __shfl_xor_sync(0xffffffffu, sum2, off);
    }
    int warp = tid >> 5, lanei = tid & 31;
    if (lanei == 0) { red[0][warp] = sum; red[1][warp] = sum2; }
    __syncthreads();
    if (warp == 0) {
        float s  = (lanei < 8) ? red[0][lanei] : 0.f;
        float s2 = (lanei < 8) ? red[1][lanei] : 0.f;
        #pragma unroll
        for (int off = 4; off > 0; off >>= 1) {
            s  += __shfl_xor_sync(0xffffffffu, s,  off);
            s2 += __shfl_xor_sync(0xffffffffu, s2, off);
        }
        if (lanei == 0) { red[0][0] = s; red[1][0] = s2; }
    }
    __syncthreads();
    float mean = red[0][0] * (1.f / HIDDEN);
    float var  = red[1][0] * (1.f / HIDDEN) - mean*mean;
    float rstd = rsqrtf(var + EPS);

    float4 gv = *(const float4*)&gamma[tid*4];
    float4 bv = *(const float4*)&beta [tid*4];
    float4 ov;
    ov.x = (h0 - mean) * rstd * gv.x + bv.x;
    ov.y = (h1 - mean) * rstd * gv.y + bv.y;
    ov.z = (h2 - mean) * rstd * gv.z + bv.z;
    ov.w = (h3 - mean) * rstd * gv.w + bv.w;
    *(float4*)&orow[tid*4] = ov;
}

// ---------------------------------------------------------------------------
extern "C" void kernel_launch(void* const* d_in, const int* in_sizes, int n_in,
                              void* d_out, int out_size)
{
    const float* x     = (const float*)d_in[0];
    const float* Wq    = (const float*)d_in[1];
    const float* Wk    = (const float*)d_in[2];
    const float* Wv    = (const float*)d_in[3];
    const float* gamma = (const float*)d_in[4];
    const float* beta  = (const float*)d_in[5];
    float* out = (float*)d_out;

    convert_kernel<<<dim3(1024, 4), 256>>>(x, Wq, Wk, Wv);
    qkv_gemm_kernel<<<dim3(NROWS/128, HIDDEN/128, 3), 256>>>();
    attn_kernel<<<dim3(SEQ/128, BATCH*NHEADS), 256>>>();
    ln_kernel<<<NROWS, 256>>>(x, gamma, beta, out);
}